// round 9
// baseline (speedup 1.0000x reference)
#include <cuda_runtime.h>
#include <cuda_bf16.h>
#include <cstdint>

#define HH 128
#define WW 128
#define HWSZ (128*128)
#define CIN 64
#define COUT 64
#define BATCH 8

// scratch (__device__ globals: allocation-free)
__device__ float g_off[BATCH * 27 * HWSZ];   // [b][27][H][W]
__device__ float g_xt[(size_t)BATCH * HWSZ * CIN];  // NHWC repack of x (33.5 MB)
// B weight fragments for mma.sync m16n8k16, main weights:
// u32 index = ((s*8 + j)*32 + lane)*2 + b ; s = kk*4+cc, j = n8 block(8), b = k-half
__device__ uint32_t g_wfh[36 * 8 * 32 * 2];
__device__ uint32_t g_wfl[36 * 8 * 32 * 2];
// conv_om weight fragments (N=32: 27 outputs zero-padded), 4 n8 blocks
__device__ uint32_t g_cfh[36 * 4 * 32 * 2];
__device__ uint32_t g_cfl[36 * 4 * 32 * 2];

static __device__ __forceinline__ uint32_t bf16pk(float a, float b) {
    __nv_bfloat16 ha = __float2bfloat16(a);
    __nv_bfloat16 hb = __float2bfloat16(b);
    return (uint32_t)__bfloat16_as_ushort(ha)
         | ((uint32_t)__bfloat16_as_ushort(hb) << 16);
}

// ---- transpose: x NCHW -> g_xt NHWC ----
__global__ __launch_bounds__(256) void trans_kernel(const float* __restrict__ x) {
    __shared__ float ts[64][65];
    int t = threadIdx.x;
    int b = blockIdx.y;
    int p0 = blockIdx.x * 64;
    const float* xb = x + (size_t)b * CIN * HWSZ;
#pragma unroll
    for (int i = 0; i < 16; i++) {
        int idx = i * 256 + t;
        int c = idx >> 6, p = idx & 63;
        ts[p][c] = xb[(size_t)c * HWSZ + p0 + p];
    }
    __syncthreads();
    float* ob = g_xt + ((size_t)b * HWSZ + p0) * 64;
#pragma unroll
    for (int i = 0; i < 16; i++) {
        int idx = i * 256 + t;
        int p = idx >> 6, c = idx & 63;
        ob[p * 64 + c] = ts[p][c];
    }
}

// ---- prep: pack both weight sets into HMMA fragments (bf16 hi/lo split) ----
__global__ void prep_kernel(const float* __restrict__ weight,
                            const float* __restrict__ ow,
                            const float* __restrict__ mw) {
    int i = blockIdx.x * blockDim.x + threadIdx.x;
    if (i < 36 * 8 * 32 * 2) {
        int bb = i & 1;
        int lane = (i >> 1) & 31;
        int j = (i >> 6) & 7;
        int s = i >> 9;                 // 0..35
        int kk = s >> 2;
        int cc = s & 3;
        int kr = 2 * (lane & 3) + 8 * bb;
        int oc = j * 8 + (lane >> 2);
        int c0 = cc * 16 + kr;
        float w0 = weight[oc * 576 + c0 * 9 + kk];
        float w1 = weight[oc * 576 + (c0 + 1) * 9 + kk];
        __nv_bfloat16 h0 = __float2bfloat16(w0);
        __nv_bfloat16 h1 = __float2bfloat16(w1);
        g_wfh[i] = (uint32_t)__bfloat16_as_ushort(h0)
                 | ((uint32_t)__bfloat16_as_ushort(h1) << 16);
        g_wfl[i] = bf16pk(w0 - __bfloat162float(h0), w1 - __bfloat162float(h1));
    }
    if (i < 36 * 4 * 32 * 2) {
        int bb = i & 1;
        int lane = (i >> 1) & 31;
        int j = (i >> 6) & 3;
        int s = i >> 8;                 // 0..35
        int kk = s >> 2;
        int cc = s & 3;
        int kr = 2 * (lane & 3) + 8 * bb;
        int o = j * 8 + (lane >> 2);
        int c0 = cc * 16 + kr;
        float w0 = 0.f, w1 = 0.f;
        if (o < 18) {
            w0 = ow[o * 576 + c0 * 9 + kk];
            w1 = ow[o * 576 + (c0 + 1) * 9 + kk];
        } else if (o < 27) {
            w0 = mw[(o - 18) * 576 + c0 * 9 + kk];
            w1 = mw[(o - 18) * 576 + (c0 + 1) * 9 + kk];
        }
        __nv_bfloat16 h0 = __float2bfloat16(w0);
        __nv_bfloat16 h1 = __float2bfloat16(w1);
        g_cfh[i] = (uint32_t)__bfloat16_as_ushort(h0)
                 | ((uint32_t)__bfloat16_as_ushort(h1) << 16);
        g_cfl[i] = bf16pk(w0 - __bfloat162float(h0), w1 - __bfloat162float(h1));
    }
}

static __device__ __forceinline__ void mma_bf16(float* d, uint32_t a0, uint32_t a1,
                                                uint32_t a2, uint32_t a3,
                                                uint32_t b0, uint32_t b1) {
    asm volatile(
        "mma.sync.aligned.m16n8k16.row.col.f32.bf16.bf16.f32 "
        "{%0,%1,%2,%3}, {%4,%5,%6,%7}, {%8,%9}, {%0,%1,%2,%3};"
        : "+f"(d[0]), "+f"(d[1]), "+f"(d[2]), "+f"(d[3])
        : "r"(a0), "r"(a1), "r"(a2), "r"(a3), "r"(b0), "r"(b1));
}

// ---- kernel 1 v3: offset+modulator conv as pipelined HMMA GEMM (NHWC input) ----
__global__ __launch_bounds__(256, 2) void conv_om_kernel(const float* __restrict__ ob,
                                                         const float* __restrict__ mb) {
    __shared__ uint32_t wBh[4 * 4 * 32 * 2];                  // 4 KB
    __shared__ uint32_t wBl[4 * 4 * 32 * 2];                  // 4 KB
    __shared__ __align__(16) unsigned short vSh[2][128][16];  // 8 KB
    __shared__ __align__(16) unsigned short vSl[2][128][16];  // 8 KB

    int t = threadIdx.x;
    int wid = t >> 5;
    int lid = t & 31;
    int ho = blockIdx.x;
    int b = blockIdx.y;
    const float* xtb = g_xt + (size_t)b * HWSZ * 64;

    int sp = t & 127;
    int cl0 = (t >> 7) * 8;

    int pos0 = wid * 16;
    int r4 = lid >> 2;
    int q4 = lid & 3;

    float acc[4][4];
#pragma unroll
    for (int j = 0; j < 4; j++)
#pragma unroll
        for (int q = 0; q < 4; q++) acc[j][q] = 0.f;

    auto stage = [&](int it, int buf) {
        int kk = it >> 2;
        int cc = it & 3;
        int ki = kk / 3, kj = kk - ki * 3;
        int yo = ho - 1 + ki;
        int xo = sp - 1 + kj;
        bool valid = ((unsigned)yo < HH) && ((unsigned)xo < WW);
        float v[8];
        if (valid) {
            const float4* p = (const float4*)(xtb + (size_t)(yo * WW + xo) * 64
                                              + cc * 16 + cl0);
            float4 u0 = __ldg(p), u1 = __ldg(p + 1);
            v[0] = u0.x; v[1] = u0.y; v[2] = u0.z; v[3] = u0.w;
            v[4] = u1.x; v[5] = u1.y; v[6] = u1.z; v[7] = u1.w;
        } else {
#pragma unroll
            for (int i = 0; i < 8; i++) v[i] = 0.f;
        }
        uint32_t ph[4], pl[4];
#pragma unroll
        for (int j = 0; j < 4; j++) {
            __nv_bfloat16 h0 = __float2bfloat16(v[2 * j]);
            __nv_bfloat16 h1 = __float2bfloat16(v[2 * j + 1]);
            ph[j] = (uint32_t)__bfloat16_as_ushort(h0)
                  | ((uint32_t)__bfloat16_as_ushort(h1) << 16);
            pl[j] = bf16pk(v[2 * j] - __bfloat162float(h0),
                           v[2 * j + 1] - __bfloat162float(h1));
        }
        *(uint4*)&vSh[buf][sp][cl0] = make_uint4(ph[0], ph[1], ph[2], ph[3]);
        *(uint4*)&vSl[buf][sp][cl0] = make_uint4(pl[0], pl[1], pl[2], pl[3]);
    };

    stage(0, 0);

#pragma unroll 1
    for (int it = 0; it < 36; it++) {
        int kk = it >> 2;
        int cc = it & 3;
        int buf = it & 1;

        __syncthreads();

        if (cc == 0) {
            ((uint4*)wBh)[t] = ((const uint4*)(g_cfh + kk * 1024))[t];
            ((uint4*)wBl)[t] = ((const uint4*)(g_cfl + kk * 1024))[t];
        }

        if (it + 1 < 36) stage(it + 1, buf ^ 1);

        if (cc == 0) __syncthreads();

        {
            const char* bhp = (const char*)&vSh[buf][0][0];
            const char* blp = (const char*)&vSl[buf][0][0];
            uint32_t aoff = (uint32_t)((pos0 + r4) * 32 + q4 * 4);
            uint32_t ah0 = *(const uint32_t*)(bhp + aoff);
            uint32_t ah1 = *(const uint32_t*)(bhp + aoff + 256);
            uint32_t ah2 = *(const uint32_t*)(bhp + aoff + 16);
            uint32_t ah3 = *(const uint32_t*)(bhp + aoff + 256 + 16);
            uint32_t al0 = *(const uint32_t*)(blp + aoff);
            uint32_t al1 = *(const uint32_t*)(blp + aoff + 256);
            uint32_t al2 = *(const uint32_t*)(blp + aoff + 16);
            uint32_t al3 = *(const uint32_t*)(blp + aoff + 256 + 16);
            const uint2* wbh = (const uint2*)&wBh[cc * 256];
            const uint2* wbl = (const uint2*)&wBl[cc * 256];
#pragma unroll
            for (int j = 0; j < 4; j++) {
                uint2 bh2 = wbh[j * 32 + lid];
                uint2 bl2 = wbl[j * 32 + lid];
                mma_bf16(acc[j], ah0, ah1, ah2, ah3, bh2.x, bh2.y);
                mma_bf16(acc[j], ah0, ah1, ah2, ah3, bl2.x, bl2.y);
                mma_bf16(acc[j], al0, al1, al2, al3, bh2.x, bh2.y);
            }
        }
    }

    float* base = g_off + (size_t)b * 27 * HWSZ + ho * WW;
#pragma unroll
    for (int j = 0; j < 4; j++) {
        int oc0 = j * 8 + 2 * q4;
#pragma unroll
        for (int h = 0; h < 2; h++) {
            int o = oc0 + h;
            if (o < 27) {
                float v0 = acc[j][h];
                float v1 = acc[j][h + 2];
                if (o < 18) {
                    float bb = __ldg(ob + o);
                    v0 += bb; v1 += bb;
                } else {
                    float bb = __ldg(mb + o - 18);
                    v0 = 2.f / (1.f + __expf(-(v0 + bb)));
                    v1 = 2.f / (1.f + __expf(-(v1 + bb)));
                }
                base[(size_t)o * HWSZ + pos0 + r4] = v0;
                base[(size_t)o * HWSZ + pos0 + r4 + 8] = v1;
            }
        }
    }
}

// ---- bilinear tap metadata ----
struct Tap { float a00, a01, a10, a11; int o00, o01, o10, o11; };

static __device__ __forceinline__ Tap mk_tap(const float* __restrict__ offb,
                                             int pos, int ho, int xi,
                                             int ki, int kj) {
    Tap t;
    float dy = offb[(2 * ki * 3 + 2 * kj) * HWSZ + pos];
    float dx = offb[(2 * ki * 3 + 2 * kj + 1) * HWSZ + pos];
    float m  = offb[(18 + ki * 3 + kj) * HWSZ + pos];
    float fy = (float)(ho - 1 + ki) + dy;
    float fx = (float)(xi - 1 + kj) + dx;
    float fy0 = floorf(fy), fx0 = floorf(fx);
    int iy0 = (int)fy0, ix0 = (int)fx0;
    float wy = fy - fy0, wx = fx - fx0;
    bool vy0 = (unsigned)iy0 < HH;
    bool vy1 = (unsigned)(iy0 + 1) < HH;
    bool vx0 = (unsigned)ix0 < WW;
    bool vx1 = (unsigned)(ix0 + 1) < WW;
    t.a00 = (1.f - wy) * (1.f - wx) * m * ((vy0 && vx0) ? 1.f : 0.f);
    t.a01 = (1.f - wy) * wx         * m * ((vy0 && vx1) ? 1.f : 0.f);
    t.a10 = wy * (1.f - wx)         * m * ((vy1 && vx0) ? 1.f : 0.f);
    t.a11 = wy * wx                 * m * ((vy1 && vx1) ? 1.f : 0.f);
    int cy0 = min(max(iy0, 0), HH - 1);
    int cy1 = min(max(iy0 + 1, 0), HH - 1);
    int cx0 = min(max(ix0, 0), WW - 1);
    int cx1 = min(max(ix0 + 1, 0), WW - 1);
    t.o00 = cy0 * WW + cx0; t.o01 = cy0 * WW + cx1;
    t.o10 = cy1 * WW + cx0; t.o11 = cy1 * WW + cx1;
    return t;
}

// ---- kernel 2 v6: NHWC vectorized gather -> bf16-split smem -> HMMA ----
__global__ __launch_bounds__(256, 2) void deform_kernel(float* __restrict__ out) {
    __shared__ uint32_t wBh[4 * 8 * 32 * 2];                       // 8 KB
    __shared__ uint32_t wBl[4 * 8 * 32 * 2];                       // 8 KB
    __shared__ __align__(16) unsigned short vSh[2][128][16];       // 8 KB
    __shared__ __align__(16) unsigned short vSl[2][128][16];       // 8 KB

    int t = threadIdx.x;
    int wid = t >> 5;
    int lid = t & 31;
    int ho = blockIdx.x;
    int b = blockIdx.y;
    const float* xtb = g_xt + (size_t)b * HWSZ * 64;
    const float* offb = g_off + (size_t)b * 27 * HWSZ;

    int sp = t & 127;
    int cl0 = (t >> 7) * 8;
    int spos = ho * WW + sp;

    int pos0 = wid * 16;
    int r4 = lid >> 2;
    int q4 = lid & 3;

    float acc[8][4];
#pragma unroll
    for (int j = 0; j < 8; j++)
#pragma unroll
        for (int q = 0; q < 4; q++) acc[j][q] = 0.f;

    Tap tp = mk_tap(offb, spos, ho, sp, 0, 0);

    auto gather = [&](const Tap& g, int cc, float* v) {
        const float* xc = xtb + cc * 16 + cl0;
        const float4* p00 = (const float4*)(xc + (size_t)g.o00 * 64);
        const float4* p01 = (const float4*)(xc + (size_t)g.o01 * 64);
        const float4* p10 = (const float4*)(xc + (size_t)g.o10 * 64);
        const float4* p11 = (const float4*)(xc + (size_t)g.o11 * 64);
        float4 a0 = __ldg(p00), a1 = __ldg(p00 + 1);
        float4 b0 = __ldg(p01), b1 = __ldg(p01 + 1);
        float4 c0 = __ldg(p10), c1 = __ldg(p10 + 1);
        float4 d0 = __ldg(p11), d1 = __ldg(p11 + 1);
        v[0] = g.a00 * a0.x + g.a01 * b0.x + g.a10 * c0.x + g.a11 * d0.x;
        v[1] = g.a00 * a0.y + g.a01 * b0.y + g.a10 * c0.y + g.a11 * d0.y;
        v[2] = g.a00 * a0.z + g.a01 * b0.z + g.a10 * c0.z + g.a11 * d0.z;
        v[3] = g.a00 * a0.w + g.a01 * b0.w + g.a10 * c0.w + g.a11 * d0.w;
        v[4] = g.a00 * a1.x + g.a01 * b1.x + g.a10 * c1.x + g.a11 * d1.x;
        v[5] = g.a00 * a1.y + g.a01 * b1.y + g.a10 * c1.y + g.a11 * d1.y;
        v[6] = g.a00 * a1.z + g.a01 * b1.z + g.a10 * c1.z + g.a11 * d1.z;
        v[7] = g.a00 * a1.w + g.a01 * b1.w + g.a10 * c1.w + g.a11 * d1.w;
    };

    auto split_store = [&](const float* v, int buf) {
        uint32_t ph[4], pl[4];
#pragma unroll
        for (int j = 0; j < 4; j++) {
            __nv_bfloat16 h0 = __float2bfloat16(v[2 * j]);
            __nv_bfloat16 h1 = __float2bfloat16(v[2 * j + 1]);
            ph[j] = (uint32_t)__bfloat16_as_ushort(h0)
                  | ((uint32_t)__bfloat16_as_ushort(h1) << 16);
            pl[j] = bf16pk(v[2 * j] - __bfloat162float(h0),
                           v[2 * j + 1] - __bfloat162float(h1));
        }
        *(uint4*)&vSh[buf][sp][cl0] = make_uint4(ph[0], ph[1], ph[2], ph[3]);
        *(uint4*)&vSl[buf][sp][cl0] = make_uint4(pl[0], pl[1], pl[2], pl[3]);
    };

    // prologue: step 0
    {
        float v[8];
        gather(tp, 0, v);
        split_store(v, 0);
    }

#pragma unroll 1
    for (int it = 0; it < 36; it++) {
        int kk = it >> 2;
        int cc = it & 3;
        int buf = it & 1;

        __syncthreads();

        if (cc == 0) {
            const uint4* sh = (const uint4*)(g_wfh + kk * 2048);
            const uint4* sl = (const uint4*)(g_wfl + kk * 2048);
            ((uint4*)wBh)[t] = sh[t]; ((uint4*)wBh)[t + 256] = sh[t + 256];
            ((uint4*)wBl)[t] = sl[t]; ((uint4*)wBl)[t + 256] = sl[t + 256];
        }

        if (it + 1 < 36) {
            int itn = it + 1;
            int kkn = itn >> 2;
            int ccn = itn & 3;
            if (ccn == 0) tp = mk_tap(offb, spos, ho, sp, kkn / 3, kkn % 3);
            float v[8];
            gather(tp, ccn, v);
            split_store(v, itn & 1);
        }

        if (cc == 0) __syncthreads();

        {
            const char* bhp = (const char*)&vSh[buf][0][0];
            const char* blp = (const char*)&vSl[buf][0][0];
            uint32_t aoff = (uint32_t)((pos0 + r4) * 32 + q4 * 4);
            uint32_t ah0 = *(const uint32_t*)(bhp + aoff);
            uint32_t ah1 = *(const uint32_t*)(bhp + aoff + 256);
            uint32_t ah2 = *(const uint32_t*)(bhp + aoff + 16);
            uint32_t ah3 = *(const uint32_t*)(bhp + aoff + 256 + 16);
            uint32_t al0 = *(const uint32_t*)(blp + aoff);
            uint32_t al1 = *(const uint32_t*)(blp + aoff + 256);
            uint32_t al2 = *(const uint32_t*)(blp + aoff + 16);
            uint32_t al3 = *(const uint32_t*)(blp + aoff + 256 + 16);
            const uint2* wbh = (const uint2*)&wBh[cc * 512];
            const uint2* wbl = (const uint2*)&wBl[cc * 512];
#pragma unroll
            for (int j = 0; j < 8; j++) {
                uint2 bh2 = wbh[j * 32 + lid];
                uint2 bl2 = wbl[j * 32 + lid];
                mma_bf16(acc[j], ah0, ah1, ah2, ah3, bh2.x, bh2.y);
                mma_bf16(acc[j], ah0, ah1, ah2, ah3, bl2.x, bl2.y);
                mma_bf16(acc[j], al0, al1, al2, al3, bh2.x, bh2.y);
            }
        }
    }

    float* ob = out + (size_t)b * COUT * HWSZ + ho * WW;
#pragma unroll
    for (int j = 0; j < 8; j++) {
        int oc = j * 8 + q4 * 2;
        int p = pos0 + r4;
        ob[(size_t)oc * HWSZ + p]           = acc[j][0];
        ob[(size_t)(oc + 1) * HWSZ + p]     = acc[j][1];
        ob[(size_t)oc * HWSZ + p + 8]       = acc[j][2];
        ob[(size_t)(oc + 1) * HWSZ + p + 8] = acc[j][3];
    }
}

extern "C" void kernel_launch(void* const* d_in, const int* in_sizes, int n_in,
                              void* d_out, int out_size) {
    const float* x  = (const float*)d_in[0];  // [8,64,128,128]
    const float* ow = (const float*)d_in[1];  // [18,64,3,3]
    const float* ob = (const float*)d_in[2];  // [18]
    const float* mw = (const float*)d_in[3];  // [9,64,3,3]
    const float* mb = (const float*)d_in[4];  // [9]
    const float* wt = (const float*)d_in[5];  // [64,64,3,3]
    float* out = (float*)d_out;               // [8,64,128,128]

    prep_kernel<<<72, 256>>>(wt, ow, mw);

    dim3 gt(HWSZ / 64, BATCH);
    trans_kernel<<<gt, 256>>>(x);

    dim3 g1(HH, BATCH);
    conv_om_kernel<<<g1, 256>>>(ob, mb);

    dim3 g2(HH, BATCH);
    deform_kernel<<<g2, 256>>>(out);
}

// round 10
// speedup vs baseline: 1.2030x; 1.2030x over previous
#include <cuda_runtime.h>
#include <cuda_bf16.h>
#include <cstdint>

#define HH 128
#define WW 128
#define HWSZ (128*128)
#define CIN 64
#define COUT 64
#define BATCH 8

// scratch (__device__ globals: allocation-free)
__device__ float g_off[BATCH * 27 * HWSZ];          // [b][27][H][W]
__device__ float g_xt[(size_t)BATCH * HWSZ * CIN];  // NHWC repack of x
// B weight fragments for mma.sync m16n8k16, main weights:
// u32 index = ((s*8 + j)*32 + lane)*2 + b ; s = kk*4+cc, j = n8 block(8), b = k-half
__device__ uint32_t g_wfh[36 * 8 * 32 * 2];
__device__ uint32_t g_wfl[36 * 8 * 32 * 2];
// conv_om weight fragments (N=32: 27 outputs zero-padded), 4 n8 blocks
__device__ uint32_t g_cfh[36 * 4 * 32 * 2];
__device__ uint32_t g_cfl[36 * 4 * 32 * 2];

static __device__ __forceinline__ uint32_t bf16pk(float a, float b) {
    __nv_bfloat16 ha = __float2bfloat16(a);
    __nv_bfloat16 hb = __float2bfloat16(b);
    return (uint32_t)__bfloat16_as_ushort(ha)
         | ((uint32_t)__bfloat16_as_ushort(hb) << 16);
}

// ---- transpose: x NCHW -> g_xt NHWC ----
__global__ __launch_bounds__(256) void trans_kernel(const float* __restrict__ x) {
    __shared__ float ts[64][65];
    int t = threadIdx.x;
    int b = blockIdx.y;
    int p0 = blockIdx.x * 64;
    const float* xb = x + (size_t)b * CIN * HWSZ;
#pragma unroll
    for (int i = 0; i < 16; i++) {
        int idx = i * 256 + t;
        int c = idx >> 6, p = idx & 63;
        ts[p][c] = xb[(size_t)c * HWSZ + p0 + p];
    }
    __syncthreads();
    float* ob = g_xt + ((size_t)b * HWSZ + p0) * 64;
#pragma unroll
    for (int i = 0; i < 16; i++) {
        int idx = i * 256 + t;
        int p = idx >> 6, c = idx & 63;
        ob[p * 64 + c] = ts[p][c];
    }
}

// ---- prep: pack both weight sets into HMMA fragments (bf16 hi/lo split) ----
__global__ void prep_kernel(const float* __restrict__ weight,
                            const float* __restrict__ ow,
                            const float* __restrict__ mw) {
    int i = blockIdx.x * blockDim.x + threadIdx.x;
    if (i < 36 * 8 * 32 * 2) {
        int bb = i & 1;
        int lane = (i >> 1) & 31;
        int j = (i >> 6) & 7;
        int s = i >> 9;                 // 0..35
        int kk = s >> 2;
        int cc = s & 3;
        int kr = 2 * (lane & 3) + 8 * bb;
        int oc = j * 8 + (lane >> 2);
        int c0 = cc * 16 + kr;
        float w0 = weight[oc * 576 + c0 * 9 + kk];
        float w1 = weight[oc * 576 + (c0 + 1) * 9 + kk];
        __nv_bfloat16 h0 = __float2bfloat16(w0);
        __nv_bfloat16 h1 = __float2bfloat16(w1);
        g_wfh[i] = (uint32_t)__bfloat16_as_ushort(h0)
                 | ((uint32_t)__bfloat16_as_ushort(h1) << 16);
        g_wfl[i] = bf16pk(w0 - __bfloat162float(h0), w1 - __bfloat162float(h1));
    }
    if (i < 36 * 4 * 32 * 2) {
        int bb = i & 1;
        int lane = (i >> 1) & 31;
        int j = (i >> 6) & 3;
        int s = i >> 8;                 // 0..35
        int kk = s >> 2;
        int cc = s & 3;
        int kr = 2 * (lane & 3) + 8 * bb;
        int o = j * 8 + (lane >> 2);
        int c0 = cc * 16 + kr;
        float w0 = 0.f, w1 = 0.f;
        if (o < 18) {
            w0 = ow[o * 576 + c0 * 9 + kk];
            w1 = ow[o * 576 + (c0 + 1) * 9 + kk];
        } else if (o < 27) {
            w0 = mw[(o - 18) * 576 + c0 * 9 + kk];
            w1 = mw[(o - 18) * 576 + (c0 + 1) * 9 + kk];
        }
        __nv_bfloat16 h0 = __float2bfloat16(w0);
        __nv_bfloat16 h1 = __float2bfloat16(w1);
        g_cfh[i] = (uint32_t)__bfloat16_as_ushort(h0)
                 | ((uint32_t)__bfloat16_as_ushort(h1) << 16);
        g_cfl[i] = bf16pk(w0 - __bfloat162float(h0), w1 - __bfloat162float(h1));
    }
}

static __device__ __forceinline__ void mma_bf16(float* d, uint32_t a0, uint32_t a1,
                                                uint32_t a2, uint32_t a3,
                                                uint32_t b0, uint32_t b1) {
    asm volatile(
        "mma.sync.aligned.m16n8k16.row.col.f32.bf16.bf16.f32 "
        "{%0,%1,%2,%3}, {%4,%5,%6,%7}, {%8,%9}, {%0,%1,%2,%3};"
        : "+f"(d[0]), "+f"(d[1]), "+f"(d[2]), "+f"(d[3])
        : "r"(a0), "r"(a1), "r"(a2), "r"(a3), "r"(b0), "r"(b1));
}

// ---- kernel 1 (R8 version): offset+modulator conv as pipelined HMMA GEMM, NCHW x ----
__global__ __launch_bounds__(256, 2) void conv_om_kernel(const float* __restrict__ x,
                                                         const float* __restrict__ ob,
                                                         const float* __restrict__ mb) {
    __shared__ uint32_t wBh[4 * 4 * 32 * 2];                  // 4 KB
    __shared__ uint32_t wBl[4 * 4 * 32 * 2];                  // 4 KB
    __shared__ __align__(16) unsigned short vSh[2][128][16];  // 8 KB
    __shared__ __align__(16) unsigned short vSl[2][128][16];  // 8 KB

    int t = threadIdx.x;
    int wid = t >> 5;
    int lid = t & 31;
    int ho = blockIdx.x;
    int b = blockIdx.y;
    const float* xb = x + (size_t)b * CIN * HWSZ;

    int sp = t & 127;
    int cl0 = (t >> 7) * 8;

    int pos0 = wid * 16;
    int r4 = lid >> 2;
    int q4 = lid & 3;

    float acc[4][4];
#pragma unroll
    for (int j = 0; j < 4; j++)
#pragma unroll
        for (int q = 0; q < 4; q++) acc[j][q] = 0.f;

    auto stage = [&](int it, int buf) {
        int kk = it >> 2;
        int cc = it & 3;
        int ki = kk / 3, kj = kk - ki * 3;
        int yo = ho - 1 + ki;
        int xo = sp - 1 + kj;
        bool valid = ((unsigned)yo < HH) && ((unsigned)xo < WW);
        const float* xc = xb + (size_t)(cc * 16 + cl0) * HWSZ + yo * WW + xo;
        float v[8];
#pragma unroll
        for (int i = 0; i < 8; i++)
            v[i] = valid ? __ldg(xc + i * HWSZ) : 0.f;
        uint32_t ph[4], pl[4];
#pragma unroll
        for (int j = 0; j < 4; j++) {
            __nv_bfloat16 h0 = __float2bfloat16(v[2 * j]);
            __nv_bfloat16 h1 = __float2bfloat16(v[2 * j + 1]);
            ph[j] = (uint32_t)__bfloat16_as_ushort(h0)
                  | ((uint32_t)__bfloat16_as_ushort(h1) << 16);
            pl[j] = bf16pk(v[2 * j] - __bfloat162float(h0),
                           v[2 * j + 1] - __bfloat162float(h1));
        }
        *(uint4*)&vSh[buf][sp][cl0] = make_uint4(ph[0], ph[1], ph[2], ph[3]);
        *(uint4*)&vSl[buf][sp][cl0] = make_uint4(pl[0], pl[1], pl[2], pl[3]);
    };

    stage(0, 0);

#pragma unroll 1
    for (int it = 0; it < 36; it++) {
        int kk = it >> 2;
        int cc = it & 3;
        int buf = it & 1;

        __syncthreads();

        if (cc == 0) {
            ((uint4*)wBh)[t] = ((const uint4*)(g_cfh + kk * 1024))[t];
            ((uint4*)wBl)[t] = ((const uint4*)(g_cfl + kk * 1024))[t];
        }

        if (it + 1 < 36) stage(it + 1, buf ^ 1);

        if (cc == 0) __syncthreads();

        {
            const char* bhp = (const char*)&vSh[buf][0][0];
            const char* blp = (const char*)&vSl[buf][0][0];
            uint32_t aoff = (uint32_t)((pos0 + r4) * 32 + q4 * 4);
            uint32_t ah0 = *(const uint32_t*)(bhp + aoff);
            uint32_t ah1 = *(const uint32_t*)(bhp + aoff + 256);
            uint32_t ah2 = *(const uint32_t*)(bhp + aoff + 16);
            uint32_t ah3 = *(const uint32_t*)(bhp + aoff + 256 + 16);
            uint32_t al0 = *(const uint32_t*)(blp + aoff);
            uint32_t al1 = *(const uint32_t*)(blp + aoff + 256);
            uint32_t al2 = *(const uint32_t*)(blp + aoff + 16);
            uint32_t al3 = *(const uint32_t*)(blp + aoff + 256 + 16);
            const uint2* wbh = (const uint2*)&wBh[cc * 256];
            const uint2* wbl = (const uint2*)&wBl[cc * 256];
#pragma unroll
            for (int j = 0; j < 4; j++) {
                uint2 bh2 = wbh[j * 32 + lid];
                uint2 bl2 = wbl[j * 32 + lid];
                mma_bf16(acc[j], ah0, ah1, ah2, ah3, bh2.x, bh2.y);
                mma_bf16(acc[j], ah0, ah1, ah2, ah3, bl2.x, bl2.y);
                mma_bf16(acc[j], al0, al1, al2, al3, bh2.x, bh2.y);
            }
        }
    }

    float* base = g_off + (size_t)b * 27 * HWSZ + ho * WW;
#pragma unroll
    for (int j = 0; j < 4; j++) {
        int oc0 = j * 8 + 2 * q4;
#pragma unroll
        for (int h = 0; h < 2; h++) {
            int o = oc0 + h;
            if (o < 27) {
                float v0 = acc[j][h];
                float v1 = acc[j][h + 2];
                if (o < 18) {
                    float bb = __ldg(ob + o);
                    v0 += bb; v1 += bb;
                } else {
                    float bb = __ldg(mb + o - 18);
                    v0 = 2.f / (1.f + __expf(-(v0 + bb)));
                    v1 = 2.f / (1.f + __expf(-(v1 + bb)));
                }
                base[(size_t)o * HWSZ + pos0 + r4] = v0;
                base[(size_t)o * HWSZ + pos0 + r4 + 8] = v1;
            }
        }
    }
}

// ---- bilinear tap metadata ----
struct Tap { float a00, a01, a10, a11; int o00, o01, o10, o11; };

static __device__ __forceinline__ Tap mk_tap(const float* __restrict__ offb,
                                             int pos, int ho, int xi,
                                             int ki, int kj) {
    Tap t;
    float dy = offb[(2 * ki * 3 + 2 * kj) * HWSZ + pos];
    float dx = offb[(2 * ki * 3 + 2 * kj + 1) * HWSZ + pos];
    float m  = offb[(18 + ki * 3 + kj) * HWSZ + pos];
    float fy = (float)(ho - 1 + ki) + dy;
    float fx = (float)(xi - 1 + kj) + dx;
    float fy0 = floorf(fy), fx0 = floorf(fx);
    int iy0 = (int)fy0, ix0 = (int)fx0;
    float wy = fy - fy0, wx = fx - fx0;
    bool vy0 = (unsigned)iy0 < HH;
    bool vy1 = (unsigned)(iy0 + 1) < HH;
    bool vx0 = (unsigned)ix0 < WW;
    bool vx1 = (unsigned)(ix0 + 1) < WW;
    t.a00 = (1.f - wy) * (1.f - wx) * m * ((vy0 && vx0) ? 1.f : 0.f);
    t.a01 = (1.f - wy) * wx         * m * ((vy0 && vx1) ? 1.f : 0.f);
    t.a10 = wy * (1.f - wx)         * m * ((vy1 && vx0) ? 1.f : 0.f);
    t.a11 = wy * wx                 * m * ((vy1 && vx1) ? 1.f : 0.f);
    int cy0 = min(max(iy0, 0), HH - 1);
    int cy1 = min(max(iy0 + 1, 0), HH - 1);
    int cx0 = min(max(ix0, 0), WW - 1);
    int cx1 = min(max(ix0 + 1, 0), WW - 1);
    t.o00 = cy0 * WW + cx0; t.o01 = cy0 * WW + cx1;
    t.o10 = cy1 * WW + cx0; t.o11 = cy1 * WW + cx1;
    return t;
}

// ---- kernel 2 v7: warp-cooperative NHWC gather -> bf16-split smem -> HMMA ----
// Gather mapping: lane = p3*4 + q; p3 = 8 positions/warp, q = channel quad.
// Each lane: 4 corner float4 loads = 64B-contiguous chunks across 4 lanes.
__global__ __launch_bounds__(256, 2) void deform_kernel(float* __restrict__ out) {
    __shared__ uint32_t wBh[4 * 8 * 32 * 2];                       // 8 KB
    __shared__ uint32_t wBl[4 * 8 * 32 * 2];                       // 8 KB
    __shared__ __align__(16) unsigned short vSh[2][128][16];       // 8 KB
    __shared__ __align__(16) unsigned short vSl[2][128][16];       // 8 KB
    __shared__ __align__(16) Tap tS[128];                          // 4 KB

    int t = threadIdx.x;
    int wid = t >> 5;
    int lid = t & 31;
    int ho = blockIdx.x;
    int b = blockIdx.y;
    const float* xtb = g_xt + (size_t)b * HWSZ * 64;
    const float* offb = g_off + (size_t)b * 27 * HWSZ;

    // gather mapping
    int p3 = lid >> 2;
    int q = lid & 3;

    // gemm mapping
    int pos0 = wid * 16;
    int r4 = lid >> 2;
    int q4 = lid & 3;

    float acc[8][4];
#pragma unroll
    for (int j = 0; j < 8; j++)
#pragma unroll
        for (int qq = 0; qq < 4; qq++) acc[j][qq] = 0.f;

    auto gather = [&](int ccn, int nb) {
#pragma unroll
        for (int pass = 0; pass < 2; pass++) {
            int p = pass * 64 + wid * 8 + p3;
            Tap g = tS[p];
            const float* xc = xtb + ccn * 16 + q * 4;
            float4 vA = __ldg((const float4*)(xc + (size_t)g.o00 * 64));
            float4 vB = __ldg((const float4*)(xc + (size_t)g.o01 * 64));
            float4 vC = __ldg((const float4*)(xc + (size_t)g.o10 * 64));
            float4 vD = __ldg((const float4*)(xc + (size_t)g.o11 * 64));
            float w0 = g.a00 * vA.x + g.a01 * vB.x + g.a10 * vC.x + g.a11 * vD.x;
            float w1 = g.a00 * vA.y + g.a01 * vB.y + g.a10 * vC.y + g.a11 * vD.y;
            float w2 = g.a00 * vA.z + g.a01 * vB.z + g.a10 * vC.z + g.a11 * vD.z;
            float w3 = g.a00 * vA.w + g.a01 * vB.w + g.a10 * vC.w + g.a11 * vD.w;
            __nv_bfloat16 h0 = __float2bfloat16(w0);
            __nv_bfloat16 h1 = __float2bfloat16(w1);
            __nv_bfloat16 h2 = __float2bfloat16(w2);
            __nv_bfloat16 h3 = __float2bfloat16(w3);
            uint32_t ph0 = (uint32_t)__bfloat16_as_ushort(h0)
                         | ((uint32_t)__bfloat16_as_ushort(h1) << 16);
            uint32_t ph1 = (uint32_t)__bfloat16_as_ushort(h2)
                         | ((uint32_t)__bfloat16_as_ushort(h3) << 16);
            uint32_t pl0 = bf16pk(w0 - __bfloat162float(h0), w1 - __bfloat162float(h1));
            uint32_t pl1 = bf16pk(w2 - __bfloat162float(h2), w3 - __bfloat162float(h3));
            *(uint2*)&vSh[nb][p][q * 4] = make_uint2(ph0, ph1);
            *(uint2*)&vSl[nb][p][q * 4] = make_uint2(pl0, pl1);
        }
    };

    // prologue: taps for kk=0, stage step 0
    if (t < 128) tS[t] = mk_tap(offb, ho * WW + t, ho, t, 0, 0);
    __syncthreads();
    gather(0, 0);

#pragma unroll 1
    for (int it = 0; it < 36; it++) {
        int kk = it >> 2;
        int cc = it & 3;
        int buf = it & 1;

        __syncthreads();

        if (cc == 0) {
            const uint4* sh = (const uint4*)(g_wfh + kk * 2048);
            const uint4* sl = (const uint4*)(g_wfl + kk * 2048);
            ((uint4*)wBh)[t] = sh[t]; ((uint4*)wBh)[t + 256] = sh[t + 256];
            ((uint4*)wBl)[t] = sl[t]; ((uint4*)wBl)[t + 256] = sl[t + 256];
        }

        if (it + 1 < 36) {
            int itn = it + 1;
            int kkn = itn >> 2;
            int ccn = itn & 3;
            if (ccn == 0) {   // kk boundary: refresh tap cache
                if (t < 128)
                    tS[t] = mk_tap(offb, ho * WW + t, ho, t, kkn / 3, kkn % 3);
                __syncthreads();
            }
            gather(ccn, itn & 1);
        }

        if (cc == 0) __syncthreads();

        {
            const char* bhp = (const char*)&vSh[buf][0][0];
            const char* blp = (const char*)&vSl[buf][0][0];
            uint32_t aoff = (uint32_t)((pos0 + r4) * 32 + q4 * 4);
            uint32_t ah0 = *(const uint32_t*)(bhp + aoff);
            uint32_t ah1 = *(const uint32_t*)(bhp + aoff + 256);
            uint32_t ah2 = *(const uint32_t*)(bhp + aoff + 16);
            uint32_t ah3 = *(const uint32_t*)(bhp + aoff + 256 + 16);
            uint32_t al0 = *(const uint32_t*)(blp + aoff);
            uint32_t al1 = *(const uint32_t*)(blp + aoff + 256);
            uint32_t al2 = *(const uint32_t*)(blp + aoff + 16);
            uint32_t al3 = *(const uint32_t*)(blp + aoff + 256 + 16);
            const uint2* wbh = (const uint2*)&wBh[cc * 512];
            const uint2* wbl = (const uint2*)&wBl[cc * 512];
#pragma unroll
            for (int j = 0; j < 8; j++) {
                uint2 bh2 = wbh[j * 32 + lid];
                uint2 bl2 = wbl[j * 32 + lid];
                mma_bf16(acc[j], ah0, ah1, ah2, ah3, bh2.x, bh2.y);
                mma_bf16(acc[j], ah0, ah1, ah2, ah3, bl2.x, bl2.y);
                mma_bf16(acc[j], al0, al1, al2, al3, bh2.x, bh2.y);
            }
        }
    }

    float* ob = out + (size_t)b * COUT * HWSZ + ho * WW;
#pragma unroll
    for (int j = 0; j < 8; j++) {
        int oc = j * 8 + q4 * 2;
        int p = pos0 + r4;
        ob[(size_t)oc * HWSZ + p]           = acc[j][0];
        ob[(size_t)(oc + 1) * HWSZ + p]     = acc[j][1];
        ob[(size_t)oc * HWSZ + p + 8]       = acc[j][2];
        ob[(size_t)(oc + 1) * HWSZ + p + 8] = acc[j][3];
    }
}

extern "C" void kernel_launch(void* const* d_in, const int* in_sizes, int n_in,
                              void* d_out, int out_size) {
    const float* x  = (const float*)d_in[0];  // [8,64,128,128]
    const float* ow = (const float*)d_in[1];  // [18,64,3,3]
    const float* ob = (const float*)d_in[2];  // [18]
    const float* mw = (const float*)d_in[3];  // [9,64,3,3]
    const float* mb = (const float*)d_in[4];  // [9]
    const float* wt = (const float*)d_in[5];  // [64,64,3,3]
    float* out = (float*)d_out;               // [8,64,128,128]

    prep_kernel<<<72, 256>>>(wt, ow, mw);

    dim3 gt(HWSZ / 64, BATCH);
    trans_kernel<<<gt, 256>>>(x);

    dim3 g1(HH, BATCH);
    conv_om_kernel<<<g1, 256>>>(x, ob, mb);

    dim3 g2(HH, BATCH);
    deform_kernel<<<g2, 256>>>(out);
}

// round 11
// speedup vs baseline: 1.7890x; 1.4871x over previous
#include <cuda_runtime.h>
#include <cuda_bf16.h>
#include <cstdint>

#define HH 128
#define WW 128
#define HWSZ (128*128)
#define CIN 64
#define COUT 64
#define BATCH 8

// scratch (__device__ globals: allocation-free)
__device__ float g_off[BATCH * 27 * HWSZ];   // [b][27][H][W]
// B weight fragments for mma.sync m16n8k16 (k-permuted: ch = 4q+2bb+w):
// u32 index = ((s*8 + j)*32 + lane)*2 + bb ; s = kk*4+cc, j = n8 block(8)
__device__ uint32_t g_wfh[36 * 8 * 32 * 2];
__device__ uint32_t g_wfl[36 * 8 * 32 * 2];
// conv_om weight fragments (N=32: 27 outputs zero-padded), 4 n8 blocks
__device__ uint32_t g_cfh[36 * 4 * 32 * 2];
__device__ uint32_t g_cfl[36 * 4 * 32 * 2];

static __device__ __forceinline__ uint32_t bf16pk(float a, float b) {
    __nv_bfloat16 ha = __float2bfloat16(a);
    __nv_bfloat16 hb = __float2bfloat16(b);
    return (uint32_t)__bfloat16_as_ushort(ha)
         | ((uint32_t)__bfloat16_as_ushort(hb) << 16);
}

// ---- prep: pack both weight sets into HMMA fragments (bf16 hi/lo split) ----
// k-permutation: fragment slot (q = lane&3, bb = k-half, w) holds channel 4q+2bb+w
__global__ void prep_kernel(const float* __restrict__ weight,
                            const float* __restrict__ ow,
                            const float* __restrict__ mw) {
    int i = blockIdx.x * blockDim.x + threadIdx.x;
    if (i < 36 * 8 * 32 * 2) {
        int bb = i & 1;
        int lane = (i >> 1) & 31;
        int j = (i >> 6) & 7;
        int s = i >> 9;                 // 0..35
        int kk = s >> 2;
        int cc = s & 3;
        int kr = 4 * (lane & 3) + 2 * bb;   // permuted k
        int oc = j * 8 + (lane >> 2);
        int c0 = cc * 16 + kr;
        float w0 = weight[oc * 576 + c0 * 9 + kk];
        float w1 = weight[oc * 576 + (c0 + 1) * 9 + kk];
        __nv_bfloat16 h0 = __float2bfloat16(w0);
        __nv_bfloat16 h1 = __float2bfloat16(w1);
        g_wfh[i] = (uint32_t)__bfloat16_as_ushort(h0)
                 | ((uint32_t)__bfloat16_as_ushort(h1) << 16);
        g_wfl[i] = bf16pk(w0 - __bfloat162float(h0), w1 - __bfloat162float(h1));
    }
    if (i < 36 * 4 * 32 * 2) {
        int bb = i & 1;
        int lane = (i >> 1) & 31;
        int j = (i >> 6) & 3;
        int s = i >> 8;                 // 0..35
        int kk = s >> 2;
        int cc = s & 3;
        int kr = 4 * (lane & 3) + 2 * bb;   // permuted k
        int o = j * 8 + (lane >> 2);
        int c0 = cc * 16 + kr;
        float w0 = 0.f, w1 = 0.f;
        if (o < 18) {
            w0 = ow[o * 576 + c0 * 9 + kk];
            w1 = ow[o * 576 + (c0 + 1) * 9 + kk];
        } else if (o < 27) {
            w0 = mw[(o - 18) * 576 + c0 * 9 + kk];
            w1 = mw[(o - 18) * 576 + (c0 + 1) * 9 + kk];
        }
        __nv_bfloat16 h0 = __float2bfloat16(w0);
        __nv_bfloat16 h1 = __float2bfloat16(w1);
        g_cfh[i] = (uint32_t)__bfloat16_as_ushort(h0)
                 | ((uint32_t)__bfloat16_as_ushort(h1) << 16);
        g_cfl[i] = bf16pk(w0 - __bfloat162float(h0), w1 - __bfloat162float(h1));
    }
}

static __device__ __forceinline__ void mma_bf16(float* d, uint32_t a0, uint32_t a1,
                                                uint32_t a2, uint32_t a3,
                                                uint32_t b0, uint32_t b1) {
    asm volatile(
        "mma.sync.aligned.m16n8k16.row.col.f32.bf16.bf16.f32 "
        "{%0,%1,%2,%3}, {%4,%5,%6,%7}, {%8,%9}, {%0,%1,%2,%3};"
        : "+f"(d[0]), "+f"(d[1]), "+f"(d[2]), "+f"(d[3])
        : "r"(a0), "r"(a1), "r"(a2), "r"(a3), "r"(b0), "r"(b1));
}

// ---- kernel 1 v5: offset+modulator conv, pipelined HMMA, NCHW x, direct-LDG B ----
__global__ __launch_bounds__(256, 2) void conv_om_kernel(const float* __restrict__ x,
                                                         const float* __restrict__ ob,
                                                         const float* __restrict__ mb) {
    __shared__ __align__(16) unsigned short vSh[2][128][16];  // 8 KB
    __shared__ __align__(16) unsigned short vSl[2][128][16];  // 8 KB

    int t = threadIdx.x;
    int wid = t >> 5;
    int lid = t & 31;
    int ho = blockIdx.x;
    int b = blockIdx.y;
    const float* xb = x + (size_t)b * CIN * HWSZ;

    int sp = t & 127;
    int cl0 = (t >> 7) * 8;

    int pos0 = wid * 16;
    int r4 = lid >> 2;
    int q4 = lid & 3;

    float acc[4][4];
#pragma unroll
    for (int j = 0; j < 4; j++)
#pragma unroll
        for (int q = 0; q < 4; q++) acc[j][q] = 0.f;

    auto stage = [&](int it, int buf) {
        int kk = it >> 2;
        int cc = it & 3;
        int ki = kk / 3, kj = kk - ki * 3;
        int yo = ho - 1 + ki;
        int xo = sp - 1 + kj;
        bool valid = ((unsigned)yo < HH) && ((unsigned)xo < WW);
        const float* xc = xb + (size_t)(cc * 16 + cl0) * HWSZ + yo * WW + xo;
        float v[8];
#pragma unroll
        for (int i = 0; i < 8; i++)
            v[i] = valid ? __ldg(xc + i * HWSZ) : 0.f;
        uint32_t ph[4], pl[4];
#pragma unroll
        for (int j = 0; j < 4; j++) {
            __nv_bfloat16 h0 = __float2bfloat16(v[2 * j]);
            __nv_bfloat16 h1 = __float2bfloat16(v[2 * j + 1]);
            ph[j] = (uint32_t)__bfloat16_as_ushort(h0)
                  | ((uint32_t)__bfloat16_as_ushort(h1) << 16);
            pl[j] = bf16pk(v[2 * j] - __bfloat162float(h0),
                           v[2 * j + 1] - __bfloat162float(h1));
        }
        *(uint4*)&vSh[buf][sp][cl0] = make_uint4(ph[0], ph[1], ph[2], ph[3]);
        *(uint4*)&vSl[buf][sp][cl0] = make_uint4(pl[0], pl[1], pl[2], pl[3]);
    };

    stage(0, 0);

#pragma unroll 1
    for (int it = 0; it < 36; it++) {
        int buf = it & 1;

        __syncthreads();

        if (it + 1 < 36) stage(it + 1, buf ^ 1);

        {
            const char* bhp = (const char*)&vSh[buf][0][0];
            const char* blp = (const char*)&vSl[buf][0][0];
            uint32_t aoff = (uint32_t)((pos0 + r4) * 32 + q4 * 8);
            uint2 h0 = *(const uint2*)(bhp + aoff);          // (a0, a2)
            uint2 h1 = *(const uint2*)(bhp + aoff + 256);    // (a1, a3)
            uint2 l0 = *(const uint2*)(blp + aoff);
            uint2 l1 = *(const uint2*)(blp + aoff + 256);
#pragma unroll
            for (int j = 0; j < 4; j++) {
                uint2 bh2 = __ldg((const uint2*)&g_cfh[((it * 4 + j) * 32 + lid) * 2]);
                uint2 bl2 = __ldg((const uint2*)&g_cfl[((it * 4 + j) * 32 + lid) * 2]);
                mma_bf16(acc[j], h0.x, h1.x, h0.y, h1.y, bh2.x, bh2.y);
                mma_bf16(acc[j], h0.x, h1.x, h0.y, h1.y, bl2.x, bl2.y);
                mma_bf16(acc[j], l0.x, l1.x, l0.y, l1.y, bh2.x, bh2.y);
            }
        }
    }

    float* base = g_off + (size_t)b * 27 * HWSZ + ho * WW;
#pragma unroll
    for (int j = 0; j < 4; j++) {
        int oc0 = j * 8 + 2 * q4;
#pragma unroll
        for (int h = 0; h < 2; h++) {
            int o = oc0 + h;
            if (o < 27) {
                float v0 = acc[j][h];
                float v1 = acc[j][h + 2];
                if (o < 18) {
                    float bb = __ldg(ob + o);
                    v0 += bb; v1 += bb;
                } else {
                    float bb = __ldg(mb + o - 18);
                    v0 = 2.f / (1.f + __expf(-(v0 + bb)));
                    v1 = 2.f / (1.f + __expf(-(v1 + bb)));
                }
                base[(size_t)o * HWSZ + pos0 + r4] = v0;
                base[(size_t)o * HWSZ + pos0 + r4 + 8] = v1;
            }
        }
    }
}

// ---- bilinear tap metadata ----
struct Tap { float a00, a01, a10, a11; int o00, o01, o10, o11; };

static __device__ __forceinline__ Tap mk_tap(const float* __restrict__ offb,
                                             int pos, int ho, int xi,
                                             int ki, int kj) {
    Tap t;
    float dy = offb[(2 * ki * 3 + 2 * kj) * HWSZ + pos];
    float dx = offb[(2 * ki * 3 + 2 * kj + 1) * HWSZ + pos];
    float m  = offb[(18 + ki * 3 + kj) * HWSZ + pos];
    float fy = (float)(ho - 1 + ki) + dy;
    float fx = (float)(xi - 1 + kj) + dx;
    float fy0 = floorf(fy), fx0 = floorf(fx);
    int iy0 = (int)fy0, ix0 = (int)fx0;
    float wy = fy - fy0, wx = fx - fx0;
    bool vy0 = (unsigned)iy0 < HH;
    bool vy1 = (unsigned)(iy0 + 1) < HH;
    bool vx0 = (unsigned)ix0 < WW;
    bool vx1 = (unsigned)(ix0 + 1) < WW;
    t.a00 = (1.f - wy) * (1.f - wx) * m * ((vy0 && vx0) ? 1.f : 0.f);
    t.a01 = (1.f - wy) * wx         * m * ((vy0 && vx1) ? 1.f : 0.f);
    t.a10 = wy * (1.f - wx)         * m * ((vy1 && vx0) ? 1.f : 0.f);
    t.a11 = wy * wx                 * m * ((vy1 && vx1) ? 1.f : 0.f);
    int cy0 = min(max(iy0, 0), HH - 1);
    int cy1 = min(max(iy0 + 1, 0), HH - 1);
    int cx0 = min(max(ix0, 0), WW - 1);
    int cx1 = min(max(ix0 + 1, 0), WW - 1);
    t.o00 = cy0 * WW + cx0; t.o01 = cy0 * WW + cx1;
    t.o10 = cy1 * WW + cx0; t.o11 = cy1 * WW + cx1;
    return t;
}

// ---- kernel 2 v8: NCHW scalar gather (R8) + LDS.64 A-frags + Mw=2/Nw=4 + LDG B ----
__global__ __launch_bounds__(256, 2) void deform_kernel(const float* __restrict__ x,
                                                        float* __restrict__ out) {
    __shared__ __align__(16) unsigned short vSh[2][128][16];       // 8 KB
    __shared__ __align__(16) unsigned short vSl[2][128][16];       // 8 KB

    int t = threadIdx.x;
    int wid = t >> 5;
    int lid = t & 31;
    int ho = blockIdx.x;
    int b = blockIdx.y;
    const float* xb = x + (size_t)b * CIN * HWSZ;
    const float* offb = g_off + (size_t)b * 27 * HWSZ;

    int sp = t & 127;
    int cl0 = (t >> 7) * 8;
    int spos = ho * WW + sp;

    // gemm mapping: warp = 32 pos (2 m16 tiles) x 32 oc (4 j blocks)
    int pos0 = (wid & 3) * 32;
    int j0 = (wid >> 2) * 4;
    int r4 = lid >> 2;
    int q4 = lid & 3;

    float acc[2][4][4];
#pragma unroll
    for (int mt = 0; mt < 2; mt++)
#pragma unroll
        for (int j = 0; j < 4; j++)
#pragma unroll
            for (int q = 0; q < 4; q++) acc[mt][j][q] = 0.f;

    Tap tp = mk_tap(offb, spos, ho, sp, 0, 0);

    auto stage = [&](const Tap& g, int cc, int buf) {
        const float* xc = xb + (size_t)(cc * 16 + cl0) * HWSZ;
        float v[8];
#pragma unroll
        for (int i = 0; i < 8; i++) {
            const float* p = xc + (size_t)i * HWSZ;
            v[i] = g.a00 * __ldg(p + g.o00) + g.a01 * __ldg(p + g.o01)
                 + g.a10 * __ldg(p + g.o10) + g.a11 * __ldg(p + g.o11);
        }
        uint32_t ph[4], pl[4];
#pragma unroll
        for (int j = 0; j < 4; j++) {
            __nv_bfloat16 h0 = __float2bfloat16(v[2 * j]);
            __nv_bfloat16 h1 = __float2bfloat16(v[2 * j + 1]);
            ph[j] = (uint32_t)__bfloat16_as_ushort(h0)
                  | ((uint32_t)__bfloat16_as_ushort(h1) << 16);
            pl[j] = bf16pk(v[2 * j] - __bfloat162float(h0),
                           v[2 * j + 1] - __bfloat162float(h1));
        }
        *(uint4*)&vSh[buf][sp][cl0] = make_uint4(ph[0], ph[1], ph[2], ph[3]);
        *(uint4*)&vSl[buf][sp][cl0] = make_uint4(pl[0], pl[1], pl[2], pl[3]);
    };

    stage(tp, 0, 0);

#pragma unroll 1
    for (int it = 0; it < 36; it++) {
        int buf = it & 1;

        __syncthreads();

        if (it + 1 < 36) {
            int itn = it + 1;
            int kkn = itn >> 2;
            int ccn = itn & 3;
            if (ccn == 0) tp = mk_tap(offb, spos, ho, sp, kkn / 3, kkn % 3);
            stage(tp, ccn, itn & 1);
        }

        {
            const char* bhp = (const char*)&vSh[buf][0][0];
            const char* blp = (const char*)&vSl[buf][0][0];
            uint2 h0[2], h1[2], l0[2], l1[2];
#pragma unroll
            for (int mt = 0; mt < 2; mt++) {
                uint32_t aoff = (uint32_t)((pos0 + mt * 16 + r4) * 32 + q4 * 8);
                h0[mt] = *(const uint2*)(bhp + aoff);          // (a0, a2)
                h1[mt] = *(const uint2*)(bhp + aoff + 256);    // (a1, a3)
                l0[mt] = *(const uint2*)(blp + aoff);
                l1[mt] = *(const uint2*)(blp + aoff + 256);
            }
#pragma unroll
            for (int jj = 0; jj < 4; jj++) {
                int j = j0 + jj;
                uint2 bh2 = __ldg((const uint2*)&g_wfh[((it * 8 + j) * 32 + lid) * 2]);
                uint2 bl2 = __ldg((const uint2*)&g_wfl[((it * 8 + j) * 32 + lid) * 2]);
#pragma unroll
                for (int mt = 0; mt < 2; mt++) {
                    mma_bf16(acc[mt][jj], h0[mt].x, h1[mt].x, h0[mt].y, h1[mt].y,
                             bh2.x, bh2.y);
                    mma_bf16(acc[mt][jj], h0[mt].x, h1[mt].x, h0[mt].y, h1[mt].y,
                             bl2.x, bl2.y);
                    mma_bf16(acc[mt][jj], l0[mt].x, l1[mt].x, l0[mt].y, l1[mt].y,
                             bh2.x, bh2.y);
                }
            }
        }
    }

    float* ob = out + (size_t)b * COUT * HWSZ + ho * WW;
#pragma unroll
    for (int mt = 0; mt < 2; mt++) {
#pragma unroll
        for (int jj = 0; jj < 4; jj++) {
            int oc = (j0 + jj) * 8 + q4 * 2;
            int p = pos0 + mt * 16 + r4;
            ob[(size_t)oc * HWSZ + p]           = acc[mt][jj][0];
            ob[(size_t)(oc + 1) * HWSZ + p]     = acc[mt][jj][1];
            ob[(size_t)oc * HWSZ + p + 8]       = acc[mt][jj][2];
            ob[(size_t)(oc + 1) * HWSZ + p + 8] = acc[mt][jj][3];
        }
    }
}

extern "C" void kernel_launch(void* const* d_in, const int* in_sizes, int n_in,
                              void* d_out, int out_size) {
    const float* x  = (const float*)d_in[0];  // [8,64,128,128]
    const float* ow = (const float*)d_in[1];  // [18,64,3,3]
    const float* ob = (const float*)d_in[2];  // [18]
    const float* mw = (const float*)d_in[3];  // [9,64,3,3]
    const float* mb = (const float*)d_in[4];  // [9]
    const float* wt = (const float*)d_in[5];  // [64,64,3,3]
    float* out = (float*)d_out;               // [8,64,128,128]

    prep_kernel<<<72, 256>>>(wt, ow, mw);

    dim3 g1(HH, BATCH);
    conv_om_kernel<<<g1, 256>>>(x, ob, mb);

    dim3 g2(HH, BATCH);
    deform_kernel<<<g2, 256>>>(x, out);
}